// round 1
// baseline (speedup 1.0000x reference)
#include <cuda_runtime.h>
#include <math.h>

// Problem constants
#define Bsz 16384
#define Hd  512
#define FF  2048
#define NL  3

// GEMM tiling
#define BM 128
#define BN 128
#define BK 16

// ---------------- static device scratch (no cudaMalloc allowed) ----------------
__device__ float d_S[Bsz * Hd];        // gathered src rows (compact)
__device__ float d_T[Bsz * Hd];        // gathered tgt rows (compact)
__device__ float d_X[Bsz * Hd];        // activation x (compact)
__device__ float d_TMP[Bsz * Hd];      // attn / ffn output (compact)
__device__ float d_HB[Bsz * FF];       // ffn hidden (compact)
__device__ float d_P[NL * Hd * Hd];    // folded attn weight per layer (ao_w @ wv)
__device__ float d_CB[NL * Hd];        // folded attn bias per layer
__device__ float d_WT[Hd * Hd];        // wv transposed scratch
__device__ float d_prior[2 * Hd];      // prior vector [p_img | p_text]
__device__ float d_zb[FF];             // zero bias (zero-initialized)
__device__ int   d_idx1[Bsz];          // rows with missing_type==1 (need gen_text)
__device__ int   d_idx2[Bsz];          // rows with missing_type==2 (need gen_img)
__device__ int   d_cnt[2];

// ---------------- small kernels ----------------
__global__ void reset_cnt_kernel() { d_cnt[0] = 0; d_cnt[1] = 0; }

__global__ void build_idx_kernel(const int* __restrict__ mt) {
    int i = blockIdx.x * blockDim.x + threadIdx.x;
    if (i >= Bsz) return;
    int m = mt[i];
    if (m == 1)      d_idx1[atomicAdd(&d_cnt[0], 1)] = i;
    else if (m == 2) d_idx2[atomicAdd(&d_cnt[1], 1)] = i;
}

// gather src/tgt rows into compact buffers. grid = Bsz blocks of 128 threads.
__global__ void gather_rows_kernel(const float* __restrict__ src,
                                   const float* __restrict__ tgt,
                                   const int* __restrict__ idx,
                                   const int* __restrict__ cnt) {
    int i = blockIdx.x;
    if (i >= *cnt) return;
    int r = idx[i];
    int t = threadIdx.x;   // 128 threads, one float4 each (512 floats)
    reinterpret_cast<float4*>(d_S)[i * 128 + t] =
        reinterpret_cast<const float4*>(src)[r * 128 + t];
    reinterpret_cast<float4*>(d_T)[i * 128 + t] =
        reinterpret_cast<const float4*>(tgt)[r * 128 + t];
}

// 512x512 transpose: out[j][i] = in[i][j]
__global__ void transpose512_kernel(const float* __restrict__ in, float* __restrict__ out) {
    __shared__ float tile[32][33];
    int bx = blockIdx.x * 32, by = blockIdx.y * 32;
    int x = bx + threadIdx.x;
    #pragma unroll
    for (int j = 0; j < 32; j += 8) {
        int y = by + threadIdx.y + j;
        tile[threadIdx.y + j][threadIdx.x] = in[y * Hd + x];
    }
    __syncthreads();
    x = by + threadIdx.x;
    #pragma unroll
    for (int j = 0; j < 32; j += 8) {
        int y = bx + threadIdx.y + j;
        out[y * Hd + x] = tile[threadIdx.x][threadIdx.y + j];
    }
}

// c[n] = dot(ao_w[n,:], bv) + ao_b[n]
__global__ void combine_bias_kernel(const float* __restrict__ aow,
                                    const float* __restrict__ bv,
                                    const float* __restrict__ aob,
                                    float* __restrict__ c) {
    int n = blockIdx.x * blockDim.x + threadIdx.x;
    if (n >= Hd) return;
    float s = aob[n];
    for (int k = 0; k < Hd; k++) s += aow[n * Hd + k] * bv[k];
    c[n] = s;
}

__device__ __forceinline__ float gelu_exact(float v) {
    return 0.5f * v * (1.0f + erff(v * 0.70710678118654752440f));
}

// prior MLP: one block, 1024 threads
__global__ void prior_kernel(const float* __restrict__ pemb,
                             const float* __restrict__ w1, const float* __restrict__ b1,
                             const float* __restrict__ w2, const float* __restrict__ b2) {
    __shared__ float h1[2 * Hd];
    int j = threadIdx.x;  // 0..1023
    float s = b1[j];
    for (int k = 0; k < Hd; k++) s += pemb[k] * w1[j * Hd + k];
    h1[j] = gelu_exact(s);
    __syncthreads();
    float s2 = b2[j];
    for (int k = 0; k < 2 * Hd; k++) s2 += h1[k] * w2[j * 2 * Hd + k];
    d_prior[j] = s2;
}

// default output fill: img half = (mt==3 ? p_img : image), text half = (mt==3 ? p_text : text)
__global__ void base_fill_kernel(const float* __restrict__ img,
                                 const float* __restrict__ txt,
                                 const int* __restrict__ mt,
                                 float* __restrict__ out) {
    int i = blockIdx.x * blockDim.x + threadIdx.x;   // over Bsz*128 float4 units
    if (i >= Bsz * 128) return;
    int row = i >> 7, c4 = i & 127;
    int m = mt[row];
    const float4* pr = reinterpret_cast<const float4*>(d_prior);
    float4 a = (m == 3) ? pr[c4]       : reinterpret_cast<const float4*>(img)[i];
    float4 b = (m == 3) ? pr[128 + c4] : reinterpret_cast<const float4*>(txt)[i];
    reinterpret_cast<float4*>(out)[i] = a;                 // enhanced_img half
    reinterpret_cast<float4*>(out)[Bsz * 128 + i] = b;     // enhanced_text half
}

// x = LayerNorm(x + d) * g + b   (rows of 512, one block of 128 threads per row)
__global__ void add_ln_kernel(float* __restrict__ X, const float* __restrict__ D,
                              const float* __restrict__ g, const float* __restrict__ b,
                              const int* __restrict__ cnt) {
    int row = blockIdx.x;
    if (row >= *cnt) return;
    int t = threadIdx.x;  // 128
    float4 x = reinterpret_cast<float4*>(X)[row * 128 + t];
    float4 d = reinterpret_cast<const float4*>(D)[row * 128 + t];
    x.x += d.x; x.y += d.y; x.z += d.z; x.w += d.w;
    float s = x.x + x.y + x.z + x.w;
    float q = x.x * x.x + x.y * x.y + x.z * x.z + x.w * x.w;
    #pragma unroll
    for (int off = 16; off > 0; off >>= 1) {
        s += __shfl_xor_sync(0xffffffffu, s, off);
        q += __shfl_xor_sync(0xffffffffu, q, off);
    }
    __shared__ float ss[4], qq[4];
    int lane = t & 31, warp = t >> 5;
    if (lane == 0) { ss[warp] = s; qq[warp] = q; }
    __syncthreads();
    s = ss[0] + ss[1] + ss[2] + ss[3];
    q = qq[0] + qq[1] + qq[2] + qq[3];
    float mean = s * (1.0f / Hd);
    float var  = q * (1.0f / Hd) - mean * mean;
    float rstd = rsqrtf(var + 1e-5f);
    float4 gg = reinterpret_cast<const float4*>(g)[t];
    float4 bb = reinterpret_cast<const float4*>(b)[t];
    float4 o;
    o.x = (x.x - mean) * rstd * gg.x + bb.x;
    o.y = (x.y - mean) * rstd * gg.y + bb.y;
    o.z = (x.z - mean) * rstd * gg.z + bb.z;
    o.w = (x.w - mean) * rstd * gg.w + bb.w;
    reinterpret_cast<float4*>(X)[row * 128 + t] = o;
}

// ---------------- main GEMM: C[M,N] = A[M,K] @ W[N,K]^T + bias, with epilogues ----------------
// MODE 0: C = acc + bias
// MODE 1: C = gelu(acc + bias)
// MODE 2: scatter-blend: out[idx[m]*512 + n] = rw*Tg[m*512+n] + (1-rw)*(acc+bias)
template <int MODE>
__global__ __launch_bounds__(256) void gemm_kernel(
    const float* __restrict__ A, const float* __restrict__ W,
    const float* __restrict__ bias, float* __restrict__ C,
    int M, const int* __restrict__ cntPtr, int N, int K,
    const int* __restrict__ idx, const float* __restrict__ Tg,
    const float* __restrict__ rwPtr, float* __restrict__ outBase)
{
    int Mc = cntPtr ? *cntPtr : M;
    int mBase = blockIdx.y * BM;
    if (mBase >= Mc) return;
    int nBase = blockIdx.x * BN;

    __align__(16) __shared__ float As[2][BK][BM + 4];
    __align__(16) __shared__ float Ws[2][BK][BN + 4];

    const int tid = threadIdx.x;
    const int tr = tid / 16;     // 0..15
    const int tc = tid % 16;     // 0..15

    // load assignment: each thread owns rows ar0 and ar0+64, cols akq..akq+3
    const int ar0 = tid >> 2;
    const int akq = (tid & 3) * 4;

    float acc[8][8];
    #pragma unroll
    for (int i = 0; i < 8; i++)
        #pragma unroll
        for (int j = 0; j < 8; j++) acc[i][j] = 0.0f;

    const int KT = K / BK;

    float4 pa0, pa1, pw0, pw1;
    const float4 z4 = make_float4(0.f, 0.f, 0.f, 0.f);

    // fetch tile kt into registers
    auto fetch = [&](int kt) {
        int g0 = mBase + ar0, g1 = g0 + 64;
        size_t kk = (size_t)kt * BK + akq;
        pa0 = (g0 < Mc) ? *reinterpret_cast<const float4*>(A + (size_t)g0 * K + kk) : z4;
        pa1 = (g1 < Mc) ? *reinterpret_cast<const float4*>(A + (size_t)g1 * K + kk) : z4;
        pw0 = *reinterpret_cast<const float4*>(W + (size_t)(nBase + ar0) * K + kk);
        pw1 = *reinterpret_cast<const float4*>(W + (size_t)(nBase + ar0 + 64) * K + kk);
    };
    auto stash = [&](int buf) {
        As[buf][akq + 0][ar0] = pa0.x; As[buf][akq + 1][ar0] = pa0.y;
        As[buf][akq + 2][ar0] = pa0.z; As[buf][akq + 3][ar0] = pa0.w;
        As[buf][akq + 0][ar0 + 64] = pa1.x; As[buf][akq + 1][ar0 + 64] = pa1.y;
        As[buf][akq + 2][ar0 + 64] = pa1.z; As[buf][akq + 3][ar0 + 64] = pa1.w;
        Ws[buf][akq + 0][ar0] = pw0.x; Ws[buf][akq + 1][ar0] = pw0.y;
        Ws[buf][akq + 2][ar0] = pw0.z; Ws[buf][akq + 3][ar0] = pw0.w;
        Ws[buf][akq + 0][ar0 + 64] = pw1.x; Ws[buf][akq + 1][ar0 + 64] = pw1.y;
        Ws[buf][akq + 2][ar0 + 64] = pw1.z; Ws[buf][akq + 3][ar0 + 64] = pw1.w;
    };

    fetch(0); stash(0);
    __syncthreads();

    for (int kt = 0; kt < KT; ++kt) {
        int cur = kt & 1;
        if (kt + 1 < KT) fetch(kt + 1);
        #pragma unroll
        for (int k = 0; k < BK; k++) {
            float a[8], bb[8];
            *reinterpret_cast<float4*>(&a[0]) =
                *reinterpret_cast<const float4*>(&As[cur][k][tr * 8]);
            *reinterpret_cast<float4*>(&a[4]) =
                *reinterpret_cast<const float4*>(&As[cur][k][tr * 8 + 4]);
            *reinterpret_cast<float4*>(&bb[0]) =
                *reinterpret_cast<const float4*>(&Ws[cur][k][tc * 8]);
            *reinterpret_cast<float4*>(&bb[4]) =
                *reinterpret_cast<const float4*>(&Ws[cur][k][tc * 8 + 4]);
            #pragma unroll
            for (int i = 0; i < 8; i++)
                #pragma unroll
                for (int j = 0; j < 8; j++) acc[i][j] += a[i] * bb[j];
        }
        if (kt + 1 < KT) stash(cur ^ 1);
        __syncthreads();
    }

    // epilogue
    float r0 = 0.0f;
    if (MODE == 2) r0 = *rwPtr;
    #pragma unroll
    for (int i = 0; i < 8; i++) {
        int gr = mBase + tr * 8 + i;
        if (gr >= Mc) break;
        int orow = 0;
        if (MODE == 2) orow = idx[gr];
        #pragma unroll
        for (int j = 0; j < 8; j++) {
            int gc = nBase + tc * 8 + j;
            float v = acc[i][j] + bias[gc];
            if (MODE == 1) v = gelu_exact(v);
            if (MODE == 2) {
                outBase[(size_t)orow * Hd + gc] =
                    r0 * Tg[(size_t)gr * Hd + gc] + (1.0f - r0) * v;
            } else {
                C[(size_t)gr * N + gc] = v;
            }
        }
    }
}

// ---------------- host launch ----------------
extern "C" void kernel_launch(void* const* d_in, const int* in_sizes, int n_in,
                              void* d_out, int out_size) {
    (void)in_sizes; (void)n_in; (void)out_size;
    const float* image = (const float*)d_in[0];
    const float* text  = (const float*)d_in[1];
    const float* ipw   = (const float*)d_in[2];
    const float* ipb   = (const float*)d_in[3];
    const float* qkv_w = (const float*)d_in[4];
    const float* qkv_b = (const float*)d_in[5];
    const float* ao_w  = (const float*)d_in[6];
    const float* ao_b  = (const float*)d_in[7];
    const float* ln1g  = (const float*)d_in[8];
    const float* ln1b  = (const float*)d_in[9];
    const float* ln2g  = (const float*)d_in[10];
    const float* ln2b  = (const float*)d_in[11];
    const float* f1w   = (const float*)d_in[12];
    const float* f1b   = (const float*)d_in[13];
    const float* f2w   = (const float*)d_in[14];
    const float* f2b   = (const float*)d_in[15];
    const float* opw   = (const float*)d_in[16];
    const float* opb   = (const float*)d_in[17];
    const float* rw    = (const float*)d_in[18];
    const float* pw1   = (const float*)d_in[19];
    const float* pb1   = (const float*)d_in[20];
    const float* pw2   = (const float*)d_in[21];
    const float* pb2   = (const float*)d_in[22];
    const float* pemb  = (const float*)d_in[23];
    const int*   mt    = (const int*)d_in[24];
    float* out = (float*)d_out;

    float *S, *T, *X, *TMP, *HB, *P, *CB, *WT, *ZB;
    int *idx1, *idx2, *cnt;
    cudaGetSymbolAddress((void**)&S,   d_S);
    cudaGetSymbolAddress((void**)&T,   d_T);
    cudaGetSymbolAddress((void**)&X,   d_X);
    cudaGetSymbolAddress((void**)&TMP, d_TMP);
    cudaGetSymbolAddress((void**)&HB,  d_HB);
    cudaGetSymbolAddress((void**)&P,   d_P);
    cudaGetSymbolAddress((void**)&CB,  d_CB);
    cudaGetSymbolAddress((void**)&WT,  d_WT);
    cudaGetSymbolAddress((void**)&ZB,  d_zb);
    cudaGetSymbolAddress((void**)&idx1, d_idx1);
    cudaGetSymbolAddress((void**)&idx2, d_idx2);
    cudaGetSymbolAddress((void**)&cnt,  d_cnt);

    const int GY = (Bsz + BM - 1) / BM;   // 128

    reset_cnt_kernel<<<1, 1>>>();
    build_idx_kernel<<<(Bsz + 255) / 256, 256>>>(mt);
    prior_kernel<<<1, 1024>>>(pemb, pw1, pb1, pw2, pb2);
    base_fill_kernel<<<(Bsz * 128 + 255) / 256, 256>>>(image, text, mt, out);

    for (int g = 0; g < 2; g++) {
        const int*   idx  = g ? idx2 : idx1;
        const int*   cptr = cnt + g;
        const float* src  = g ? text : image;     // gen(1,...) has src=text
        const float* tgt  = g ? image : text;
        float* outBase = out + (g == 0 ? (size_t)Bsz * Hd : 0);  // gen_text -> text half

        // fold attention weights per layer: P_l = ao_w @ wv, CB_l = ao_w @ bv + ao_b
        for (int l = 0; l < NL; l++) {
            const float* wv   = qkv_w + ((size_t)(g * NL + l) * 3 * Hd + 2 * Hd) * Hd;
            const float* bv   = qkv_b + (size_t)(g * NL + l) * 3 * Hd + 2 * Hd;
            const float* aowl = ao_w + (size_t)(g * NL + l) * Hd * Hd;
            const float* aobl = ao_b + (size_t)(g * NL + l) * Hd;
            transpose512_kernel<<<dim3(16, 16), dim3(32, 8)>>>(wv, WT);
            gemm_kernel<0><<<dim3(Hd / BN, Hd / BM), 256>>>(
                aowl, WT, ZB, P + (size_t)l * Hd * Hd, Hd, nullptr, Hd, Hd,
                nullptr, nullptr, nullptr, nullptr);
            combine_bias_kernel<<<2, 256>>>(aowl, bv, aobl, CB + l * Hd);
        }

        gather_rows_kernel<<<Bsz, 128>>>(src, tgt, idx, cptr);

        // input projection: X = S @ ipw[g]^T + ipb[g]
        gemm_kernel<0><<<dim3(Hd / BN, GY), 256>>>(
            S, ipw + (size_t)g * Hd * Hd, ipb + (size_t)g * Hd, X,
            Bsz, cptr, Hd, Hd, nullptr, nullptr, nullptr, nullptr);

        for (int l = 0; l < NL; l++) {
            const float* l1g = ln1g + (size_t)(g * NL + l) * Hd;
            const float* l1b = ln1b + (size_t)(g * NL + l) * Hd;
            const float* l2g = ln2g + (size_t)(g * NL + l) * Hd;
            const float* l2b = ln2b + (size_t)(g * NL + l) * Hd;
            const float* f1wl = f1w + (size_t)(g * NL + l) * 4 * Hd * Hd;
            const float* f1bl = f1b + (size_t)(g * NL + l) * 4 * Hd;
            const float* f2wl = f2w + (size_t)(g * NL + l) * Hd * 4 * Hd;
            const float* f2bl = f2b + (size_t)(g * NL + l) * Hd;

            // attn (folded): TMP = T @ P_l^T + CB_l
            gemm_kernel<0><<<dim3(Hd / BN, GY), 256>>>(
                T, P + (size_t)l * Hd * Hd, CB + l * Hd, TMP,
                Bsz, cptr, Hd, Hd, nullptr, nullptr, nullptr, nullptr);
            add_ln_kernel<<<Bsz, 128>>>(X, TMP, l1g, l1b, cptr);

            // FFN
            gemm_kernel<1><<<dim3(FF / BN, GY), 256>>>(
                X, f1wl, f1bl, HB, Bsz, cptr, FF, Hd,
                nullptr, nullptr, nullptr, nullptr);
            gemm_kernel<0><<<dim3(Hd / BN, GY), 256>>>(
                HB, f2wl, f2bl, TMP, Bsz, cptr, Hd, FF,
                nullptr, nullptr, nullptr, nullptr);
            add_ln_kernel<<<Bsz, 128>>>(X, TMP, l2g, l2b, cptr);
        }

        // output projection + residual blend + scatter into final output
        gemm_kernel<2><<<dim3(Hd / BN, GY), 256>>>(
            X, opw + (size_t)g * Hd * Hd, opb + (size_t)g * Hd, nullptr,
            Bsz, cptr, Hd, Hd, idx, T, rw + g, outBase);
    }
}

// round 2
// speedup vs baseline: 1.0021x; 1.0021x over previous
#include <cuda_runtime.h>
#include <math.h>

// Problem constants
#define Bsz 16384
#define Hd  512
#define FF  2048
#define NL  3

// GEMM tiling
#define BM 128
#define BN 128
#define BK 16

// ---------------- static device scratch (no cudaMalloc allowed) ----------------
__device__ float d_S[Bsz * Hd];        // gathered src rows (compact)
__device__ float d_T[Bsz * Hd];        // gathered tgt rows (compact)
__device__ float d_X[Bsz * Hd];        // activation x (compact)
__device__ float d_TMP[Bsz * Hd];      // attn / ffn output (compact)
__device__ float d_HB[Bsz * FF];       // ffn hidden (compact)
__device__ float d_P[NL * Hd * Hd];    // folded attn weight per layer (ao_w @ wv)
__device__ float d_CB[NL * Hd];        // folded attn bias per layer
__device__ float d_WT[Hd * Hd];        // wv transposed scratch
__device__ float d_prior[2 * Hd];      // prior vector [p_img | p_text]
__device__ float d_zb[FF];             // zero bias (zero-initialized)
__device__ int   d_idx1[Bsz];          // rows with missing_type==1 (need gen_text)
__device__ int   d_idx2[Bsz];          // rows with missing_type==2 (need gen_img)
__device__ int   d_cnt[2];

// ---------------- small kernels ----------------
__global__ void reset_cnt_kernel() { d_cnt[0] = 0; d_cnt[1] = 0; }

__global__ void build_idx_kernel(const int* __restrict__ mt) {
    int i = blockIdx.x * blockDim.x + threadIdx.x;
    if (i >= Bsz) return;
    int m = mt[i];
    if (m == 1)      d_idx1[atomicAdd(&d_cnt[0], 1)] = i;
    else if (m == 2) d_idx2[atomicAdd(&d_cnt[1], 1)] = i;
}

// gather src/tgt rows into compact buffers. grid = Bsz blocks of 128 threads.
__global__ void gather_rows_kernel(const float* __restrict__ src,
                                   const float* __restrict__ tgt,
                                   const int* __restrict__ idx,
                                   const int* __restrict__ cnt) {
    int i = blockIdx.x;
    if (i >= *cnt) return;
    int r = idx[i];
    int t = threadIdx.x;   // 128 threads, one float4 each (512 floats)
    reinterpret_cast<float4*>(d_S)[i * 128 + t] =
        reinterpret_cast<const float4*>(src)[r * 128 + t];
    reinterpret_cast<float4*>(d_T)[i * 128 + t] =
        reinterpret_cast<const float4*>(tgt)[r * 128 + t];
}

// 512x512 transpose: out[j][i] = in[i][j]
__global__ void transpose512_kernel(const float* __restrict__ in, float* __restrict__ out) {
    __shared__ float tile[32][33];
    int bx = blockIdx.x * 32, by = blockIdx.y * 32;
    int x = bx + threadIdx.x;
    #pragma unroll
    for (int j = 0; j < 32; j += 8) {
        int y = by + threadIdx.y + j;
        tile[threadIdx.y + j][threadIdx.x] = in[y * Hd + x];
    }
    __syncthreads();
    x = by + threadIdx.x;
    #pragma unroll
    for (int j = 0; j < 32; j += 8) {
        int y = bx + threadIdx.y + j;
        out[y * Hd + x] = tile[threadIdx.x][threadIdx.y + j];
    }
}

// c[n] = dot(ao_w[n,:], bv) + ao_b[n]
__global__ void combine_bias_kernel(const float* __restrict__ aow,
                                    const float* __restrict__ bv,
                                    const float* __restrict__ aob,
                                    float* __restrict__ c) {
    int n = blockIdx.x * blockDim.x + threadIdx.x;
    if (n >= Hd) return;
    float s = aob[n];
    for (int k = 0; k < Hd; k++) s += aow[n * Hd + k] * bv[k];
    c[n] = s;
}

__device__ __forceinline__ float gelu_exact(float v) {
    return 0.5f * v * (1.0f + erff(v * 0.70710678118654752440f));
}

// prior MLP: one block, 1024 threads
__global__ void prior_kernel(const float* __restrict__ pemb,
                             const float* __restrict__ w1, const float* __restrict__ b1,
                             const float* __restrict__ w2, const float* __restrict__ b2) {
    __shared__ float h1[2 * Hd];
    int j = threadIdx.x;  // 0..1023
    float s = b1[j];
    for (int k = 0; k < Hd; k++) s += pemb[k] * w1[j * Hd + k];
    h1[j] = gelu_exact(s);
    __syncthreads();
    float s2 = b2[j];
    for (int k = 0; k < 2 * Hd; k++) s2 += h1[k] * w2[j * 2 * Hd + k];
    d_prior[j] = s2;
}

// default output fill: img half = (mt==3 ? p_img : image), text half = (mt==3 ? p_text : text)
__global__ void base_fill_kernel(const float* __restrict__ img,
                                 const float* __restrict__ txt,
                                 const int* __restrict__ mt,
                                 float* __restrict__ out) {
    int i = blockIdx.x * blockDim.x + threadIdx.x;   // over Bsz*128 float4 units
    if (i >= Bsz * 128) return;
    int row = i >> 7, c4 = i & 127;
    int m = mt[row];
    const float4* pr = reinterpret_cast<const float4*>(d_prior);
    float4 a = (m == 3) ? pr[c4]       : reinterpret_cast<const float4*>(img)[i];
    float4 b = (m == 3) ? pr[128 + c4] : reinterpret_cast<const float4*>(txt)[i];
    reinterpret_cast<float4*>(out)[i] = a;                 // enhanced_img half
    reinterpret_cast<float4*>(out)[Bsz * 128 + i] = b;     // enhanced_text half
}

// x = LayerNorm(x + d) * g + b   (rows of 512, one block of 128 threads per row)
__global__ void add_ln_kernel(float* __restrict__ X, const float* __restrict__ D,
                              const float* __restrict__ g, const float* __restrict__ b,
                              const int* __restrict__ cnt) {
    int row = blockIdx.x;
    if (row >= *cnt) return;
    int t = threadIdx.x;  // 128
    float4 x = reinterpret_cast<float4*>(X)[row * 128 + t];
    float4 d = reinterpret_cast<const float4*>(D)[row * 128 + t];
    x.x += d.x; x.y += d.y; x.z += d.z; x.w += d.w;
    float s = x.x + x.y + x.z + x.w;
    float q = x.x * x.x + x.y * x.y + x.z * x.z + x.w * x.w;
    #pragma unroll
    for (int off = 16; off > 0; off >>= 1) {
        s += __shfl_xor_sync(0xffffffffu, s, off);
        q += __shfl_xor_sync(0xffffffffu, q, off);
    }
    __shared__ float ss[4], qq[4];
    int lane = t & 31, warp = t >> 5;
    if (lane == 0) { ss[warp] = s; qq[warp] = q; }
    __syncthreads();
    s = ss[0] + ss[1] + ss[2] + ss[3];
    q = qq[0] + qq[1] + qq[2] + qq[3];
    float mean = s * (1.0f / Hd);
    float var  = q * (1.0f / Hd) - mean * mean;
    float rstd = rsqrtf(var + 1e-5f);
    float4 gg = reinterpret_cast<const float4*>(g)[t];
    float4 bb = reinterpret_cast<const float4*>(b)[t];
    float4 o;
    o.x = (x.x - mean) * rstd * gg.x + bb.x;
    o.y = (x.y - mean) * rstd * gg.y + bb.y;
    o.z = (x.z - mean) * rstd * gg.z + bb.z;
    o.w = (x.w - mean) * rstd * gg.w + bb.w;
    reinterpret_cast<float4*>(X)[row * 128 + t] = o;
}

// ---------------- main GEMM: C[M,N] = A[M,K] @ W[N,K]^T + bias, with epilogues ----------------
// MODE 0: C = acc + bias
// MODE 1: C = gelu(acc + bias)
// MODE 2: scatter-blend: out[idx[m]*512 + n] = rw*Tg[m*512+n] + (1-rw)*(acc+bias)
template <int MODE>
__global__ __launch_bounds__(256) void gemm_kernel(
    const float* __restrict__ A, const float* __restrict__ W,
    const float* __restrict__ bias, float* __restrict__ C,
    int M, const int* __restrict__ cntPtr, int N, int K,
    const int* __restrict__ idx, const float* __restrict__ Tg,
    const float* __restrict__ rwPtr, float* __restrict__ outBase)
{
    int Mc = cntPtr ? *cntPtr : M;
    int mBase = blockIdx.y * BM;
    if (mBase >= Mc) return;
    int nBase = blockIdx.x * BN;

    __align__(16) __shared__ float As[2][BK][BM + 4];
    __align__(16) __shared__ float Ws[2][BK][BN + 4];

    const int tid = threadIdx.x;
    const int tr = tid / 16;     // 0..15
    const int tc = tid % 16;     // 0..15

    // load assignment: each thread owns rows ar0 and ar0+64, cols akq..akq+3
    const int ar0 = tid >> 2;
    const int akq = (tid & 3) * 4;

    float acc[8][8];
    #pragma unroll
    for (int i = 0; i < 8; i++)
        #pragma unroll
        for (int j = 0; j < 8; j++) acc[i][j] = 0.0f;

    const int KT = K / BK;

    float4 pa0, pa1, pw0, pw1;
    const float4 z4 = make_float4(0.f, 0.f, 0.f, 0.f);

    // fetch tile kt into registers
    auto fetch = [&](int kt) {
        int g0 = mBase + ar0, g1 = g0 + 64;
        size_t kk = (size_t)kt * BK + akq;
        pa0 = (g0 < Mc) ? *reinterpret_cast<const float4*>(A + (size_t)g0 * K + kk) : z4;
        pa1 = (g1 < Mc) ? *reinterpret_cast<const float4*>(A + (size_t)g1 * K + kk) : z4;
        pw0 = *reinterpret_cast<const float4*>(W + (size_t)(nBase + ar0) * K + kk);
        pw1 = *reinterpret_cast<const float4*>(W + (size_t)(nBase + ar0 + 64) * K + kk);
    };
    auto stash = [&](int buf) {
        As[buf][akq + 0][ar0] = pa0.x; As[buf][akq + 1][ar0] = pa0.y;
        As[buf][akq + 2][ar0] = pa0.z; As[buf][akq + 3][ar0] = pa0.w;
        As[buf][akq + 0][ar0 + 64] = pa1.x; As[buf][akq + 1][ar0 + 64] = pa1.y;
        As[buf][akq + 2][ar0 + 64] = pa1.z; As[buf][akq + 3][ar0 + 64] = pa1.w;
        Ws[buf][akq + 0][ar0] = pw0.x; Ws[buf][akq + 1][ar0] = pw0.y;
        Ws[buf][akq + 2][ar0] = pw0.z; Ws[buf][akq + 3][ar0] = pw0.w;
        Ws[buf][akq + 0][ar0 + 64] = pw1.x; Ws[buf][akq + 1][ar0 + 64] = pw1.y;
        Ws[buf][akq + 2][ar0 + 64] = pw1.z; Ws[buf][akq + 3][ar0 + 64] = pw1.w;
    };

    fetch(0); stash(0);
    __syncthreads();

    for (int kt = 0; kt < KT; ++kt) {
        int cur = kt & 1;
        if (kt + 1 < KT) fetch(kt + 1);
        #pragma unroll
        for (int k = 0; k < BK; k++) {
            float a[8], bb[8];
            *reinterpret_cast<float4*>(&a[0]) =
                *reinterpret_cast<const float4*>(&As[cur][k][tr * 8]);
            *reinterpret_cast<float4*>(&a[4]) =
                *reinterpret_cast<const float4*>(&As[cur][k][tr * 8 + 4]);
            *reinterpret_cast<float4*>(&bb[0]) =
                *reinterpret_cast<const float4*>(&Ws[cur][k][tc * 8]);
            *reinterpret_cast<float4*>(&bb[4]) =
                *reinterpret_cast<const float4*>(&Ws[cur][k][tc * 8 + 4]);
            #pragma unroll
            for (int i = 0; i < 8; i++)
                #pragma unroll
                for (int j = 0; j < 8; j++) acc[i][j] += a[i] * bb[j];
        }
        if (kt + 1 < KT) stash(cur ^ 1);
        __syncthreads();
    }

    // epilogue
    float r0 = 0.0f;
    if (MODE == 2) r0 = *rwPtr;
    #pragma unroll
    for (int i = 0; i < 8; i++) {
        int gr = mBase + tr * 8 + i;
        if (gr >= Mc) break;
        int orow = 0;
        if (MODE == 2) orow = idx[gr];
        #pragma unroll
        for (int j = 0; j < 8; j++) {
            int gc = nBase + tc * 8 + j;
            float v = acc[i][j] + bias[gc];
            if (MODE == 1) v = gelu_exact(v);
            if (MODE == 2) {
                outBase[(size_t)orow * Hd + gc] =
                    r0 * Tg[(size_t)gr * Hd + gc] + (1.0f - r0) * v;
            } else {
                C[(size_t)gr * N + gc] = v;
            }
        }
    }
}

// ---------------- host launch ----------------
extern "C" void kernel_launch(void* const* d_in, const int* in_sizes, int n_in,
                              void* d_out, int out_size) {
    (void)in_sizes; (void)n_in; (void)out_size;
    const float* image = (const float*)d_in[0];
    const float* text  = (const float*)d_in[1];
    const float* ipw   = (const float*)d_in[2];
    const float* ipb   = (const float*)d_in[3];
    const float* qkv_w = (const float*)d_in[4];
    const float* qkv_b = (const float*)d_in[5];
    const float* ao_w  = (const float*)d_in[6];
    const float* ao_b  = (const float*)d_in[7];
    const float* ln1g  = (const float*)d_in[8];
    const float* ln1b  = (const float*)d_in[9];
    const float* ln2g  = (const float*)d_in[10];
    const float* ln2b  = (const float*)d_in[11];
    const float* f1w   = (const float*)d_in[12];
    const float* f1b   = (const float*)d_in[13];
    const float* f2w   = (const float*)d_in[14];
    const float* f2b   = (const float*)d_in[15];
    const float* opw   = (const float*)d_in[16];
    const float* opb   = (const float*)d_in[17];
    const float* rw    = (const float*)d_in[18];
    const float* pw1   = (const float*)d_in[19];
    const float* pb1   = (const float*)d_in[20];
    const float* pw2   = (const float*)d_in[21];
    const float* pb2   = (const float*)d_in[22];
    const float* pemb  = (const float*)d_in[23];
    const int*   mt    = (const int*)d_in[24];
    float* out = (float*)d_out;

    float *S, *T, *X, *TMP, *HB, *P, *CB, *WT, *ZB;
    int *idx1, *idx2, *cnt;
    cudaGetSymbolAddress((void**)&S,   d_S);
    cudaGetSymbolAddress((void**)&T,   d_T);
    cudaGetSymbolAddress((void**)&X,   d_X);
    cudaGetSymbolAddress((void**)&TMP, d_TMP);
    cudaGetSymbolAddress((void**)&HB,  d_HB);
    cudaGetSymbolAddress((void**)&P,   d_P);
    cudaGetSymbolAddress((void**)&CB,  d_CB);
    cudaGetSymbolAddress((void**)&WT,  d_WT);
    cudaGetSymbolAddress((void**)&ZB,  d_zb);
    cudaGetSymbolAddress((void**)&idx1, d_idx1);
    cudaGetSymbolAddress((void**)&idx2, d_idx2);
    cudaGetSymbolAddress((void**)&cnt,  d_cnt);

    const int GY = (Bsz + BM - 1) / BM;   // 128

    reset_cnt_kernel<<<1, 1>>>();
    build_idx_kernel<<<(Bsz + 255) / 256, 256>>>(mt);
    prior_kernel<<<1, 1024>>>(pemb, pw1, pb1, pw2, pb2);
    base_fill_kernel<<<(Bsz * 128 + 255) / 256, 256>>>(image, text, mt, out);

    for (int g = 0; g < 2; g++) {
        const int*   idx  = g ? idx2 : idx1;
        const int*   cptr = cnt + g;
        const float* src  = g ? text : image;     // gen(1,...) has src=text
        const float* tgt  = g ? image : text;
        float* outBase = out + (g == 0 ? (size_t)Bsz * Hd : 0);  // gen_text -> text half

        // fold attention weights per layer: P_l = ao_w @ wv, CB_l = ao_w @ bv + ao_b
        for (int l = 0; l < NL; l++) {
            const float* wv   = qkv_w + ((size_t)(g * NL + l) * 3 * Hd + 2 * Hd) * Hd;
            const float* bv   = qkv_b + (size_t)(g * NL + l) * 3 * Hd + 2 * Hd;
            const float* aowl = ao_w + (size_t)(g * NL + l) * Hd * Hd;
            const float* aobl = ao_b + (size_t)(g * NL + l) * Hd;
            transpose512_kernel<<<dim3(16, 16), dim3(32, 8)>>>(wv, WT);
            gemm_kernel<0><<<dim3(Hd / BN, Hd / BM), 256>>>(
                aowl, WT, ZB, P + (size_t)l * Hd * Hd, Hd, nullptr, Hd, Hd,
                nullptr, nullptr, nullptr, nullptr);
            combine_bias_kernel<<<2, 256>>>(aowl, bv, aobl, CB + l * Hd);
        }

        gather_rows_kernel<<<Bsz, 128>>>(src, tgt, idx, cptr);

        // input projection: X = S @ ipw[g]^T + ipb[g]
        gemm_kernel<0><<<dim3(Hd / BN, GY), 256>>>(
            S, ipw + (size_t)g * Hd * Hd, ipb + (size_t)g * Hd, X,
            Bsz, cptr, Hd, Hd, nullptr, nullptr, nullptr, nullptr);

        for (int l = 0; l < NL; l++) {
            const float* l1g = ln1g + (size_t)(g * NL + l) * Hd;
            const float* l1b = ln1b + (size_t)(g * NL + l) * Hd;
            const float* l2g = ln2g + (size_t)(g * NL + l) * Hd;
            const float* l2b = ln2b + (size_t)(g * NL + l) * Hd;
            const float* f1wl = f1w + (size_t)(g * NL + l) * 4 * Hd * Hd;
            const float* f1bl = f1b + (size_t)(g * NL + l) * 4 * Hd;
            const float* f2wl = f2w + (size_t)(g * NL + l) * Hd * 4 * Hd;
            const float* f2bl = f2b + (size_t)(g * NL + l) * Hd;

            // attn (folded): TMP = T @ P_l^T + CB_l
            gemm_kernel<0><<<dim3(Hd / BN, GY), 256>>>(
                T, P + (size_t)l * Hd * Hd, CB + l * Hd, TMP,
                Bsz, cptr, Hd, Hd, nullptr, nullptr, nullptr, nullptr);
            add_ln_kernel<<<Bsz, 128>>>(X, TMP, l1g, l1b, cptr);

            // FFN
            gemm_kernel<1><<<dim3(FF / BN, GY), 256>>>(
                X, f1wl, f1bl, HB, Bsz, cptr, FF, Hd,
                nullptr, nullptr, nullptr, nullptr);
            gemm_kernel<0><<<dim3(Hd / BN, GY), 256>>>(
                HB, f2wl, f2bl, TMP, Bsz, cptr, Hd, FF,
                nullptr, nullptr, nullptr, nullptr);
            add_ln_kernel<<<Bsz, 128>>>(X, TMP, l2g, l2b, cptr);
        }

        // output projection + residual blend + scatter into final output
        gemm_kernel<2><<<dim3(Hd / BN, GY), 256>>>(
            X, opw + (size_t)g * Hd * Hd, opb + (size_t)g * Hd, nullptr,
            Bsz, cptr, Hd, Hd, idx, T, rw + g, outBase);
    }
}